// round 5
// baseline (speedup 1.0000x reference)
#include <cuda_runtime.h>
#include <math_constants.h>

#define BB 32
#define SS 4096
#define HH 1024
#define KSPLIT 16
#define KCH (HH / KSPLIT)   // 64
#define BG 8                 // batches per v_k block
#define NBG (BB / BG)        // 4 batch groups
#define HX (HH / 256)        // 4 h-tiles

// Scratch (allocation-free rule: __device__ globals; zero-initialized)
__device__ float g_vp[KSPLIT][BB * HH];    // split-K partials of v = hid @ W (2 MB)
__device__ float g_v[BB * HH];             // reduced v
__device__ unsigned int g_vcnt[NBG][HX];   // v_k segment completion counters
__device__ unsigned int g_cnt[BB];         // score_k per-batch completion counters

// ---------------------------------------------------------------------------
// v = hid @ W with split-K partials + fused last-block reduction.
// grid (HX, KSPLIT, NBG) = (4, 16, 4) = 256 blocks x 256 threads.
// W loads pipelined 8-deep for MLP. bias term dropped (softmax shift-invariant).
// ---------------------------------------------------------------------------
__global__ void v_k(const float* __restrict__ hidden, const float* __restrict__ W) {
    __shared__ float sh[BG * KCH];  // 2 KB
    __shared__ unsigned int is_last;

    const int hx = blockIdx.x;
    const int ks = blockIdx.y;
    const int bg = blockIdx.z;
    const int k0 = ks * KCH;
    const int h  = hx * 256 + threadIdx.x;

    for (int i = threadIdx.x; i < BG * KCH; i += 256) {
        int j = i / KCH, k = i % KCH;
        sh[i] = hidden[(bg * BG + j) * HH + k0 + k];
    }
    __syncthreads();

    float acc[BG];
    #pragma unroll
    for (int j = 0; j < BG; j++) acc[j] = 0.f;

    for (int kk = 0; kk < KCH; kk += 8) {
        float wv[8];
        #pragma unroll
        for (int u = 0; u < 8; u++)
            wv[u] = W[(size_t)(k0 + kk + u) * HH + h];   // 8 independent LDGs
        #pragma unroll
        for (int u = 0; u < 8; u++)
            #pragma unroll
            for (int j = 0; j < BG; j++)
                acc[j] += sh[j * KCH + kk + u] * wv[u];
    }
    #pragma unroll
    for (int j = 0; j < BG; j++)
        g_vp[ks][(bg * BG + j) * HH + h] = acc[j];

    // ---- elect last KSPLIT-block for this (hx, bg) segment; reduce in place ----
    __threadfence();
    __syncthreads();
    if (threadIdx.x == 0)
        is_last = (atomicAdd(&g_vcnt[bg][hx], 1u) == KSPLIT - 1u) ? 1u : 0u;
    __syncthreads();
    if (!is_last) return;

    #pragma unroll
    for (int j = 0; j < BG; j++) {
        const int idx = (bg * BG + j) * HH + h;
        float s = 0.f;
        #pragma unroll
        for (int p = 0; p < KSPLIT; p++) s += __ldcg(&g_vp[p][idx]);  // L2-coherent
        g_v[idx] = s;
    }
    if (threadIdx.x == 0) g_vcnt[bg][hx] = 0u;  // reset for next graph replay
}

// ---------------------------------------------------------------------------
// Energies + fused softmax.
// grid (SS/32, BB) = (128, 32), block 256 = 8 warps x 4 rows/warp.
// Phase 1 (all blocks): out[b,s] = enc[b,s,:] . v[b,:]   (plain loads — R1's
//   proven 84%-DRAM pattern; __ldcs regressed it in R4)
// Phase 2 (last block per batch row): softmax, staged entirely in shared
//   memory so the hot phase keeps its register budget (R4 regression fix).
// ---------------------------------------------------------------------------
__global__ void __launch_bounds__(256) score_k(const float* __restrict__ enc,
                                               float* __restrict__ out) {
    __shared__ float sbuf[SS];      // 16 KB; first 4 KB doubles as staged v[b]
    __shared__ float red[8];
    __shared__ float bcast;
    __shared__ unsigned int is_last;

    const int b = blockIdx.y;
    float4* sv = reinterpret_cast<float4*>(sbuf);   // sv[0..255] = v[b]
    for (int i = threadIdx.x; i < HH / 4; i += 256)
        sv[i] = reinterpret_cast<const float4*>(g_v + b * HH)[i];
    __syncthreads();

    const int w = threadIdx.x >> 5, lane = threadIdx.x & 31;
    const int s0 = blockIdx.x * 32 + w * 4;

    #pragma unroll
    for (int r = 0; r < 4; r++) {
        const int s = s0 + r;
        const float4* row =
            reinterpret_cast<const float4*>(enc + (size_t)b * SS * HH + (size_t)s * HH);
        float acc = 0.f;
        #pragma unroll
        for (int i = 0; i < 8; i++) {
            float4 e = row[lane + i * 32];
            float4 v = sv[lane + i * 32];
            acc += e.x * v.x + e.y * v.y + e.z * v.z + e.w * v.w;
        }
        #pragma unroll
        for (int o = 16; o; o >>= 1) acc += __shfl_xor_sync(0xffffffffu, acc, o);
        if (lane == 0) out[b * SS + s] = acc;
    }

    // ---- release our writes, elect the last block for this batch row ----
    __threadfence();
    __syncthreads();
    if (threadIdx.x == 0) {
        unsigned int last = (atomicAdd(&g_cnt[b], 1u) == gridDim.x - 1u) ? 1u : 0u;
        is_last = last;
        if (last) g_cnt[b] = 0u;  // reset for next graph replay
    }
    __syncthreads();
    if (!is_last) return;
    __threadfence();  // acquire: all writers' stores now visible via L2

    // ---- softmax over out[b, 0:4096], row staged in sbuf (no extra regs) ----
    float* rowp = out + b * SS;
    float4* s4 = reinterpret_cast<float4*>(sbuf);

    float mx = -CUDART_INF_F;
    for (int i = threadIdx.x; i < SS / 4; i += 256) {
        float4 t = __ldcg(reinterpret_cast<const float4*>(rowp) + i);
        s4[i] = t;
        mx = fmaxf(mx, fmaxf(fmaxf(t.x, t.y), fmaxf(t.z, t.w)));
    }
    #pragma unroll
    for (int o = 16; o; o >>= 1) mx = fmaxf(mx, __shfl_xor_sync(0xffffffffu, mx, o));
    if (lane == 0) red[w] = mx;
    __syncthreads();
    if (threadIdx.x == 0) {
        float m = red[0];
        #pragma unroll
        for (int i = 1; i < 8; i++) m = fmaxf(m, red[i]);
        bcast = m;
    }
    __syncthreads();
    mx = bcast;

    float sum = 0.f;
    for (int i = threadIdx.x; i < SS; i += 256) {
        float e = __expf(sbuf[i] - mx);
        sbuf[i] = e;
        sum += e;
    }
    #pragma unroll
    for (int o = 16; o; o >>= 1) sum += __shfl_xor_sync(0xffffffffu, sum, o);
    if (lane == 0) red[w] = sum;
    __syncthreads();
    if (threadIdx.x == 0) {
        float s = red[0];
        #pragma unroll
        for (int i = 1; i < 8; i++) s += red[i];
        bcast = s;
    }
    __syncthreads();
    const float inv = 1.0f / bcast;

    for (int i = threadIdx.x; i < SS / 4; i += 256) {
        float4 t = s4[i];
        t.x *= inv; t.y *= inv; t.z *= inv; t.w *= inv;
        reinterpret_cast<float4*>(rowp)[i] = t;
    }
}

extern "C" void kernel_launch(void* const* d_in, const int* in_sizes, int n_in,
                              void* d_out, int out_size) {
    const float* hidden = (const float*)d_in[0];  // [B,1,H]
    const float* enc    = (const float*)d_in[1];  // [B,S,H]
    const float* W      = (const float*)d_in[2];  // [H,H]
    // d_in[3] = bias — unused: constant per row under softmax
    float* out = (float*)d_out;                   // [B,S]

    v_k<<<dim3(HX, KSPLIT, NBG), 256>>>(hidden, W);
    score_k<<<dim3(SS / 32, BB), 256>>>(enc, out);
}

// round 6
// speedup vs baseline: 1.0351x; 1.0351x over previous
#include <cuda_runtime.h>
#include <math_constants.h>

#define BB 32
#define SS 4096
#define HH 1024
#define KSPLIT 16
#define KCH (HH / KSPLIT)   // 64
#define BG 8                 // batches per v_k block
#define NBG (BB / BG)        // 4 batch groups
#define HX (HH / 256)        // 4 h-tiles

// Scratch (allocation-free rule: __device__ globals; zero-initialized)
__device__ float g_vp[KSPLIT][BB * HH];    // split-K partials of v = hid @ W (2 MB)
__device__ float g_v[BB * HH];             // reduced v
__device__ unsigned int g_vcnt[NBG][HX];   // v_k segment completion counters

// ---------------------------------------------------------------------------
// v = hid @ W with split-K partials + fused last-block reduction.
// grid (HX, KSPLIT, NBG) = (4, 16, 4) = 256 blocks x 256 threads.
// W loads pipelined 8-deep for MLP. bias term dropped (softmax shift-invariant).
// ---------------------------------------------------------------------------
__global__ void v_k(const float* __restrict__ hidden, const float* __restrict__ W) {
    __shared__ float sh[BG * KCH];  // 2 KB
    __shared__ unsigned int is_last;

    const int hx = blockIdx.x;
    const int ks = blockIdx.y;
    const int bg = blockIdx.z;
    const int k0 = ks * KCH;
    const int h  = hx * 256 + threadIdx.x;

    for (int i = threadIdx.x; i < BG * KCH; i += 256) {
        int j = i / KCH, k = i % KCH;
        sh[i] = hidden[(bg * BG + j) * HH + k0 + k];
    }
    __syncthreads();

    float acc[BG];
    #pragma unroll
    for (int j = 0; j < BG; j++) acc[j] = 0.f;

    for (int kk = 0; kk < KCH; kk += 8) {
        float wv[8];
        #pragma unroll
        for (int u = 0; u < 8; u++)
            wv[u] = W[(size_t)(k0 + kk + u) * HH + h];   // 8 independent LDGs
        #pragma unroll
        for (int u = 0; u < 8; u++)
            #pragma unroll
            for (int j = 0; j < BG; j++)
                acc[j] += sh[j * KCH + kk + u] * wv[u];
    }
    #pragma unroll
    for (int j = 0; j < BG; j++)
        g_vp[ks][(bg * BG + j) * HH + h] = acc[j];

    // ---- elect last KSPLIT-block for this (hx, bg) segment; reduce in place ----
    __threadfence();
    __syncthreads();
    if (threadIdx.x == 0)
        is_last = (atomicAdd(&g_vcnt[bg][hx], 1u) == KSPLIT - 1u) ? 1u : 0u;
    __syncthreads();
    if (!is_last) return;

    #pragma unroll
    for (int j = 0; j < BG; j++) {
        const int idx = (bg * BG + j) * HH + h;
        float s = 0.f;
        #pragma unroll
        for (int p = 0; p < KSPLIT; p++) s += __ldcg(&g_vp[p][idx]);  // L2-coherent
        g_v[idx] = s;
    }
    if (threadIdx.x == 0) g_vcnt[bg][hx] = 0u;  // reset for next graph replay
}

// ---------------------------------------------------------------------------
// Energies ONLY — exact R1 structure (81 us @ 84.3% DRAM proven).
// grid (SS/32, BB) = (128, 32), block 256 = 8 warps x 4 rows/warp.
// No fence, no atomics, no epilogue: nothing perturbs the streaming pipeline.
// ---------------------------------------------------------------------------
__global__ void score_k(const float* __restrict__ enc, float* __restrict__ out) {
    __shared__ float4 sv[HH / 4];  // v[b] staged, 4 KB
    const int b = blockIdx.y;
    for (int i = threadIdx.x; i < HH / 4; i += 256)
        sv[i] = reinterpret_cast<const float4*>(g_v + b * HH)[i];
    __syncthreads();

    const int w = threadIdx.x >> 5, lane = threadIdx.x & 31;
    const int s0 = blockIdx.x * 32 + w * 4;

    #pragma unroll
    for (int r = 0; r < 4; r++) {
        const int s = s0 + r;
        const float4* row =
            reinterpret_cast<const float4*>(enc + (size_t)b * SS * HH + (size_t)s * HH);
        float acc = 0.f;
        #pragma unroll
        for (int i = 0; i < 8; i++) {
            float4 e = row[lane + i * 32];
            float4 v = sv[lane + i * 32];
            acc += e.x * v.x + e.y * v.y + e.z * v.z + e.w * v.w;
        }
        #pragma unroll
        for (int o = 16; o; o >>= 1) acc += __shfl_xor_sync(0xffffffffu, acc, o);
        if (lane == 0) out[b * SS + s] = acc;
    }
}

// ---------------------------------------------------------------------------
// Softmax in place over each row of 4096. grid BB, block 1024, 4 elems/thread.
// ---------------------------------------------------------------------------
__global__ void softmax_k(float* __restrict__ out) {
    __shared__ float red[32];
    __shared__ float bcast;
    float* row = out + blockIdx.x * SS;
    const int w = threadIdx.x >> 5, lane = threadIdx.x & 31;

    float vals[4];
    float mx = -CUDART_INF_F;
    #pragma unroll
    for (int i = 0; i < 4; i++) {
        vals[i] = row[threadIdx.x + i * 1024];
        mx = fmaxf(mx, vals[i]);
    }
    #pragma unroll
    for (int o = 16; o; o >>= 1) mx = fmaxf(mx, __shfl_xor_sync(0xffffffffu, mx, o));
    if (lane == 0) red[w] = mx;
    __syncthreads();
    if (w == 0) {
        float m = red[lane];
        #pragma unroll
        for (int o = 16; o; o >>= 1) m = fmaxf(m, __shfl_xor_sync(0xffffffffu, m, o));
        if (lane == 0) bcast = m;
    }
    __syncthreads();
    mx = bcast;

    float sum = 0.f;
    #pragma unroll
    for (int i = 0; i < 4; i++) {
        vals[i] = __expf(vals[i] - mx);
        sum += vals[i];
    }
    #pragma unroll
    for (int o = 16; o; o >>= 1) sum += __shfl_xor_sync(0xffffffffu, sum, o);
    if (lane == 0) red[w] = sum;
    __syncthreads();
    if (w == 0) {
        float s = red[lane];
        #pragma unroll
        for (int o = 16; o; o >>= 1) s += __shfl_xor_sync(0xffffffffu, s, o);
        if (lane == 0) bcast = s;
    }
    __syncthreads();
    const float inv = 1.0f / bcast;

    #pragma unroll
    for (int i = 0; i < 4; i++)
        row[threadIdx.x + i * 1024] = vals[i] * inv;
}

extern "C" void kernel_launch(void* const* d_in, const int* in_sizes, int n_in,
                              void* d_out, int out_size) {
    const float* hidden = (const float*)d_in[0];  // [B,1,H]
    const float* enc    = (const float*)d_in[1];  // [B,S,H]
    const float* W      = (const float*)d_in[2];  // [H,H]
    // d_in[3] = bias — unused: constant per row under softmax
    float* out = (float*)d_out;                   // [B,S]

    v_k<<<dim3(HX, KSPLIT, NBG), 256>>>(hidden, W);
    score_k<<<dim3(SS / 32, BB), 256>>>(enc, out);
    softmax_k<<<BB, 1024>>>(out);
}

// round 7
// speedup vs baseline: 1.1016x; 1.0642x over previous
#include <cuda_runtime.h>
#include <math_constants.h>

#define BB 32
#define SS 4096
#define HH 1024
#define KSPLIT 32
#define KCH (HH / KSPLIT)   // 32
#define HX 4                 // h-tiles of 256
#define HTW 256              // h-tile width

// Scratch (allocation-free rule: __device__ globals; zero-initialized)
__device__ float g_vp[KSPLIT][BB * HH];   // split-K partials of v = hid @ W (4 MB)
__device__ float g_v[BB * HH];            // reduced v
__device__ unsigned int g_vcnt[HX];       // partials-complete counters
__device__ unsigned int g_vdone[HX];      // reduction-complete counters (for reset)

// ---------------------------------------------------------------------------
// v = hid @ W, single kernel: split-K partials + spin-synchronized reduction.
// grid (HX, KSPLIT) = (4, 32) = 128 blocks x 256 thr -> all resident (1/SM),
// so the intra-kernel spin cannot deadlock.
// Key: 32 FMAs amortize every W load (R2's winning ratio), W loads batched
// 8-deep for MLP, hidden read via broadcast LDS.128 from [k][b] layout.
// bias term dropped (softmax is shift-invariant).
// ---------------------------------------------------------------------------
__global__ void __launch_bounds__(256) v_k(const float* __restrict__ hidden,
                                           const float* __restrict__ W) {
    __shared__ float sh[KCH * BB];  // [k][b], 4 KB
    const int hx = blockIdx.x;
    const int ks = blockIdx.y;
    const int k0 = ks * KCH;
    const int h  = hx * HTW + threadIdx.x;

    for (int i = threadIdx.x; i < KCH * BB; i += 256) {
        int k = i / BB, b = i % BB;
        sh[i] = hidden[b * HH + k0 + k];
    }
    __syncthreads();

    float acc[BB];
    #pragma unroll
    for (int b = 0; b < BB; b++) acc[b] = 0.f;

    #pragma unroll
    for (int kk = 0; kk < KCH; kk += 8) {
        float wv[8];
        #pragma unroll
        for (int u = 0; u < 8; u++)
            wv[u] = W[(size_t)(k0 + kk + u) * HH + h];   // 8 independent LDGs
        #pragma unroll
        for (int u = 0; u < 8; u++) {
            const float4* hb4 = reinterpret_cast<const float4*>(&sh[(kk + u) * BB]);
            #pragma unroll
            for (int j = 0; j < BB / 4; j++) {
                float4 hv = hb4[j];                       // broadcast LDS.128
                acc[j * 4 + 0] += hv.x * wv[u];
                acc[j * 4 + 1] += hv.y * wv[u];
                acc[j * 4 + 2] += hv.z * wv[u];
                acc[j * 4 + 3] += hv.w * wv[u];
            }
        }
    }
    #pragma unroll
    for (int b = 0; b < BB; b++)
        g_vp[ks][b * HH + h] = acc[b];

    // ---- publish partials, spin until all KSPLIT blocks of this hx done ----
    __threadfence();
    __syncthreads();
    if (threadIdx.x == 0) {
        atomicAdd(&g_vcnt[hx], 1u);
        while (atomicAdd(&g_vcnt[hx], 0u) < KSPLIT) { }   // L2-coherent spin
    }
    __syncthreads();

    // ---- cooperative reduction: block ks reduces batch row b = ks ----
    {
        const int idx = ks * HH + h;   // KSPLIT == BB
        float s = 0.f;
        #pragma unroll
        for (int p = 0; p < KSPLIT; p++) s += __ldcg(&g_vp[p][idx]);
        g_v[idx] = s;
    }

    // ---- last finisher per hx resets counters for the next graph replay ----
    __threadfence();
    __syncthreads();
    if (threadIdx.x == 0) {
        if (atomicAdd(&g_vdone[hx], 1u) == KSPLIT - 1u) {
            g_vcnt[hx] = 0u;
            g_vdone[hx] = 0u;
        }
    }
}

// ---------------------------------------------------------------------------
// Energies ONLY — R1 structure (81 us @ 84.3% DRAM proven).
// grid (SS/32, BB) = (128, 32), block 256 = 8 warps x 4 rows/warp.
// ---------------------------------------------------------------------------
__global__ void score_k(const float* __restrict__ enc, float* __restrict__ out) {
    __shared__ float4 sv[HH / 4];  // v[b] staged, 4 KB
    const int b = blockIdx.y;
    for (int i = threadIdx.x; i < HH / 4; i += 256)
        sv[i] = reinterpret_cast<const float4*>(g_v + b * HH)[i];
    __syncthreads();

    const int w = threadIdx.x >> 5, lane = threadIdx.x & 31;
    const int s0 = blockIdx.x * 32 + w * 4;

    #pragma unroll
    for (int r = 0; r < 4; r++) {
        const int s = s0 + r;
        const float4* row =
            reinterpret_cast<const float4*>(enc + (size_t)b * SS * HH + (size_t)s * HH);
        float acc = 0.f;
        #pragma unroll
        for (int i = 0; i < 8; i++) {
            float4 e = row[lane + i * 32];
            float4 v = sv[lane + i * 32];
            acc += e.x * v.x + e.y * v.y + e.z * v.z + e.w * v.w;
        }
        #pragma unroll
        for (int o = 16; o; o >>= 1) acc += __shfl_xor_sync(0xffffffffu, acc, o);
        if (lane == 0) out[b * SS + s] = acc;
    }
}

// ---------------------------------------------------------------------------
// Softmax in place over each row of 4096. grid BB, block 1024, 4 elems/thread.
// ---------------------------------------------------------------------------
__global__ void softmax_k(float* __restrict__ out) {
    __shared__ float red[32];
    __shared__ float bcast;
    float* row = out + blockIdx.x * SS;
    const int w = threadIdx.x >> 5, lane = threadIdx.x & 31;

    float vals[4];
    float mx = -CUDART_INF_F;
    #pragma unroll
    for (int i = 0; i < 4; i++) {
        vals[i] = row[threadIdx.x + i * 1024];
        mx = fmaxf(mx, vals[i]);
    }
    #pragma unroll
    for (int o = 16; o; o >>= 1) mx = fmaxf(mx, __shfl_xor_sync(0xffffffffu, mx, o));
    if (lane == 0) red[w] = mx;
    __syncthreads();
    if (w == 0) {
        float m = red[lane];
        #pragma unroll
        for (int o = 16; o; o >>= 1) m = fmaxf(m, __shfl_xor_sync(0xffffffffu, m, o));
        if (lane == 0) bcast = m;
    }
    __syncthreads();
    mx = bcast;

    float sum = 0.f;
    #pragma unroll
    for (int i = 0; i < 4; i++) {
        vals[i] = __expf(vals[i] - mx);
        sum += vals[i];
    }
    #pragma unroll
    for (int o = 16; o; o >>= 1) sum += __shfl_xor_sync(0xffffffffu, sum, o);
    if (lane == 0) red[w] = sum;
    __syncthreads();
    if (w == 0) {
        float s = red[lane];
        #pragma unroll
        for (int o = 16; o; o >>= 1) s += __shfl_xor_sync(0xffffffffu, s, o);
        if (lane == 0) bcast = s;
    }
    __syncthreads();
    const float inv = 1.0f / bcast;

    #pragma unroll
    for (int i = 0; i < 4; i++)
        row[threadIdx.x + i * 1024] = vals[i] * inv;
}

extern "C" void kernel_launch(void* const* d_in, const int* in_sizes, int n_in,
                              void* d_out, int out_size) {
    const float* hidden = (const float*)d_in[0];  // [B,1,H]
    const float* enc    = (const float*)d_in[1];  // [B,S,H]
    const float* W      = (const float*)d_in[2];  // [H,H]
    // d_in[3] = bias — unused: constant per row under softmax
    float* out = (float*)d_out;                   // [B,S]

    v_k<<<dim3(HX, KSPLIT), 256>>>(hidden, W);
    score_k<<<dim3(SS / 32, BB), 256>>>(enc, out);
    softmax_k<<<BB, 1024>>>(out);
}

// round 8
// speedup vs baseline: 1.1063x; 1.0043x over previous
#include <cuda_runtime.h>
#include <math_constants.h>

#define BB 32
#define SS 4096
#define HH 1024
#define KSPLIT 32
#define KCH (HH / KSPLIT)   // 32
#define HX 4                 // h-tiles of 256
#define HTW 256              // h-tile width

// Scratch (allocation-free rule: __device__ globals; zero-initialized)
__device__ float g_vp[KSPLIT][BB * HH];   // split-K partials of v = hid @ W (4 MB)
__device__ float g_v[BB * HH];            // reduced v
__device__ unsigned int g_vcnt[HX];       // partials-complete counters
__device__ unsigned int g_vdone[HX];      // reduction-complete counters (for reset)

// ---------------------------------------------------------------------------
// v = hid @ W, single kernel: split-K partials + spin-synchronized reduction.
// grid (HX, KSPLIT) = (4, 32) = 128 blocks x 256 thr -> all resident (1/SM),
// so the intra-kernel spin cannot deadlock.
// R8 fixes vs R7: (a) all 32 W loads issued back-to-back (MLP 32, one DRAM
// latency exposure), (b) spin polls with ld.acquire + nanosleep instead of
// hammering the L2 atomic ALU with atomicAdd(&cnt,0).
// bias term dropped (softmax is shift-invariant).
// ---------------------------------------------------------------------------
__global__ void __launch_bounds__(256) v_k(const float* __restrict__ hidden,
                                           const float* __restrict__ W) {
    __shared__ float sh[KCH * BB];  // [k][b], 4 KB
    const int hx = blockIdx.x;
    const int ks = blockIdx.y;
    const int k0 = ks * KCH;
    const int h  = hx * HTW + threadIdx.x;

    for (int i = threadIdx.x; i < KCH * BB; i += 256) {
        int k = i / BB, b = i % BB;
        sh[i] = hidden[b * HH + k0 + k];
    }
    __syncthreads();

    // ---- all KCH W loads in flight at once (MLP = 32) ----
    float wv[KCH];
    #pragma unroll
    for (int u = 0; u < KCH; u++)
        wv[u] = W[(size_t)(k0 + u) * HH + h];

    float acc[BB];
    #pragma unroll
    for (int b = 0; b < BB; b++) acc[b] = 0.f;

    #pragma unroll
    for (int u = 0; u < KCH; u++) {
        const float4* hb4 = reinterpret_cast<const float4*>(&sh[u * BB]);
        #pragma unroll
        for (int j = 0; j < BB / 4; j++) {
            float4 hv = hb4[j];                       // broadcast LDS.128
            acc[j * 4 + 0] += hv.x * wv[u];
            acc[j * 4 + 1] += hv.y * wv[u];
            acc[j * 4 + 2] += hv.z * wv[u];
            acc[j * 4 + 3] += hv.w * wv[u];
        }
    }
    #pragma unroll
    for (int b = 0; b < BB; b++)
        g_vp[ks][b * HH + h] = acc[b];

    // ---- publish partials; spin (load + backoff) until hx's 32 blocks done ----
    __threadfence();
    __syncthreads();
    if (threadIdx.x == 0) {
        atomicAdd(&g_vcnt[hx], 1u);    // single atomic per block
        unsigned int c;
        do {
            asm volatile("ld.acquire.gpu.u32 %0, [%1];"
                         : "=r"(c) : "l"(&g_vcnt[hx]) : "memory");
            if (c < KSPLIT) __nanosleep(64);
        } while (c < KSPLIT);
    }
    __syncthreads();

    // ---- cooperative reduction: block ks reduces batch row b = ks ----
    {
        const int idx = ks * HH + h;   // KSPLIT == BB
        float s = 0.f;
        #pragma unroll
        for (int p = 0; p < KSPLIT; p++) s += __ldcg(&g_vp[p][idx]);
        g_v[idx] = s;
    }

    // ---- last finisher per hx resets counters for the next graph replay ----
    __threadfence();
    __syncthreads();
    if (threadIdx.x == 0) {
        if (atomicAdd(&g_vdone[hx], 1u) == KSPLIT - 1u) {
            g_vcnt[hx] = 0u;
            g_vdone[hx] = 0u;
        }
    }
}

// ---------------------------------------------------------------------------
// Energies ONLY — R1 structure (81 us @ 84.3% DRAM proven). Untouched.
// grid (SS/32, BB) = (128, 32), block 256 = 8 warps x 4 rows/warp.
// ---------------------------------------------------------------------------
__global__ void score_k(const float* __restrict__ enc, float* __restrict__ out) {
    __shared__ float4 sv[HH / 4];  // v[b] staged, 4 KB
    const int b = blockIdx.y;
    for (int i = threadIdx.x; i < HH / 4; i += 256)
        sv[i] = reinterpret_cast<const float4*>(g_v + b * HH)[i];
    __syncthreads();

    const int w = threadIdx.x >> 5, lane = threadIdx.x & 31;
    const int s0 = blockIdx.x * 32 + w * 4;

    #pragma unroll
    for (int r = 0; r < 4; r++) {
        const int s = s0 + r;
        const float4* row =
            reinterpret_cast<const float4*>(enc + (size_t)b * SS * HH + (size_t)s * HH);
        float acc = 0.f;
        #pragma unroll
        for (int i = 0; i < 8; i++) {
            float4 e = row[lane + i * 32];
            float4 v = sv[lane + i * 32];
            acc += e.x * v.x + e.y * v.y + e.z * v.z + e.w * v.w;
        }
        #pragma unroll
        for (int o = 16; o; o >>= 1) acc += __shfl_xor_sync(0xffffffffu, acc, o);
        if (lane == 0) out[b * SS + s] = acc;
    }
}

// ---------------------------------------------------------------------------
// Softmax in place over each row of 4096. grid BB, block 1024, 4 elems/thread.
// ---------------------------------------------------------------------------
__global__ void softmax_k(float* __restrict__ out) {
    __shared__ float red[32];
    __shared__ float bcast;
    float* row = out + blockIdx.x * SS;
    const int w = threadIdx.x >> 5, lane = threadIdx.x & 31;

    float vals[4];
    float mx = -CUDART_INF_F;
    #pragma unroll
    for (int i = 0; i < 4; i++) {
        vals[i] = row[threadIdx.x + i * 1024];
        mx = fmaxf(mx, vals[i]);
    }
    #pragma unroll
    for (int o = 16; o; o >>= 1) mx = fmaxf(mx, __shfl_xor_sync(0xffffffffu, mx, o));
    if (lane == 0) red[w] = mx;
    __syncthreads();
    if (w == 0) {
        float m = red[lane];
        #pragma unroll
        for (int o = 16; o; o >>= 1) m = fmaxf(m, __shfl_xor_sync(0xffffffffu, m, o));
        if (lane == 0) bcast = m;
    }
    __syncthreads();
    mx = bcast;

    float sum = 0.f;
    #pragma unroll
    for (int i = 0; i < 4; i++) {
        vals[i] = __expf(vals[i] - mx);
        sum += vals[i];
    }
    #pragma unroll
    for (int o = 16; o; o >>= 1) sum += __shfl_xor_sync(0xffffffffu, sum, o);
    if (lane == 0) red[w] = sum;
    __syncthreads();
    if (w == 0) {
        float s = red[lane];
        #pragma unroll
        for (int o = 16; o; o >>= 1) s += __shfl_xor_sync(0xffffffffu, s, o);
        if (lane == 0) bcast = s;
    }
    __syncthreads();
    const float inv = 1.0f / bcast;

    #pragma unroll
    for (int i = 0; i < 4; i++)
        row[threadIdx.x + i * 1024] = vals[i] * inv;
}

extern "C" void kernel_launch(void* const* d_in, const int* in_sizes, int n_in,
                              void* d_out, int out_size) {
    const float* hidden = (const float*)d_in[0];  // [B,1,H]
    const float* enc    = (const float*)d_in[1];  // [B,S,H]
    const float* W      = (const float*)d_in[2];  // [H,H]
    // d_in[3] = bias — unused: constant per row under softmax
    float* out = (float*)d_out;                   // [B,S]

    v_k<<<dim3(HX, KSPLIT), 256>>>(hidden, W);
    score_k<<<dim3(SS / 32, BB), 256>>>(enc, out);
    softmax_k<<<BB, 1024>>>(out);
}